// round 8
// baseline (speedup 1.0000x reference)
#include <cuda_runtime.h>
#include <cuda_bf16.h>
#include <stdint.h>
#include <math.h>

typedef __nv_bfloat16 bf;

#define Bb 8
#define Cc 256
#define Nn 4096
#define NG 256
#define NCH 64
#define BNC (Bb*Nn*Cc)
#define BGC (Bb*NG*Cc)

// ---------------- scratch (static __device__ — no allocation) ----------------
__device__ bf    g_xs[BNC];
__device__ bf    g_u[BNC];
__device__ float g_a[BNC];
__device__ float g_b[BNC];
__device__ bf    g_o[BNC];
__device__ bf    g_yf[BNC];
__device__ bf    g_yb[BNC];
__device__ bf    g_y[BNC];
__device__ bf    g_ygs[BNC];
__device__ bf    g_z[BNC];
__device__ bf    g_vmap[BNC];
__device__ bf    g_vt[BNC];
__device__ bf    g_v[BNC];
__device__ bf    g_tmp[BNC];
__device__ bf    g_uo[BNC];
__device__ float g_posf[Nn*Cc];
__device__ float g_posg[NG*Cc];
__device__ float g_mpart[Bb*256*Cc];
__device__ bf    g_cctx[Bb*Cc];
__device__ bf    g_cctx2[Bb*Cc];
__device__ float g_Ach[Bb*NCH*Cc];
__device__ float g_Bchf[Bb*NCH*Cc];
__device__ float g_Bchb[Bb*NCH*Cc];
__device__ float g_Sinf[Bb*NCH*Cc];
__device__ float g_Sinb[Bb*NCH*Cc];
__device__ float g_xgt[BGC];
__device__ bf    g_xgs[BGC];
__device__ bf    g_ug[BGC];
__device__ float g_a2[BGC];
__device__ float g_b2[BGC];
__device__ bf    g_o2[BGC];
__device__ bf    g_yg[BGC];

__device__ __forceinline__ float b2f(bf x) { return __bfloat162float(x); }

// ---------------- transpose [B,C,Ntok] f32 -> [B,Ntok,C] bf16 ----------------
__global__ void trans_cn_nc(const float* __restrict__ in, bf* __restrict__ outp, int Ntok) {
    __shared__ float tile[32][33];
    int b = blockIdx.z;
    int n0 = blockIdx.x * 32, c0 = blockIdx.y * 32;
    int tx = threadIdx.x, ty = threadIdx.y;
    for (int i = ty; i < 32; i += 8)
        tile[i][tx] = in[((size_t)(b * Cc + c0 + i)) * Ntok + n0 + tx];
    __syncthreads();
    for (int i = ty; i < 32; i += 8)
        outp[((size_t)(b * Ntok + n0 + i)) * Cc + c0 + tx] = __float2bfloat16(tile[tx][i]);
}

// ---------------- transpose [B,C,Ntok] bf16 -> [B,Ntok,C] bf16 ----------------
__global__ void trans_cn_nc_bf(const bf* __restrict__ in, bf* __restrict__ outp, int Ntok) {
    __shared__ bf tile[32][33];
    int b = blockIdx.z;
    int n0 = blockIdx.x * 32, c0 = blockIdx.y * 32;
    int tx = threadIdx.x, ty = threadIdx.y;
    for (int i = ty; i < 32; i += 8)
        tile[i][tx] = in[((size_t)(b * Cc + c0 + i)) * Ntok + n0 + tx];
    __syncthreads();
    for (int i = ty; i < 32; i += 8)
        outp[((size_t)(b * Ntok + n0 + i)) * Cc + c0 + tx] = tile[tx][i];
}

// ---------------- transpose-add: out[b,c,n] = x[b,c,n] + proj_bf16[b,n,c] ----------------
__global__ void trans_add_k(const bf* __restrict__ proj, const float* __restrict__ x,
                            float* __restrict__ outp) {
    __shared__ float tile[32][33];
    int b = blockIdx.z;
    int n0 = blockIdx.x * 32, c0 = blockIdx.y * 32;
    int tx = threadIdx.x, ty = threadIdx.y;
    for (int i = ty; i < 32; i += 8)
        tile[i][tx] = b2f(proj[((size_t)(b * Nn + n0 + i)) * Cc + c0 + tx]);
    __syncthreads();
    for (int i = ty; i < 32; i += 8) {
        size_t idx = ((size_t)(b * Cc + c0 + i)) * Nn + n0 + tx;
        outp[idx] = x[idx] + tile[tx][i];
    }
}

// ---------------- pos embed upsample 32->64, out fp32 [4096, 256] ----------------
__global__ void pos_up_k(const float* __restrict__ pos, float* __restrict__ outp) {
    int n = blockIdx.x, c = threadIdx.x;
    int h = n >> 6, w = n & 63;
    float sy = h * 0.5f - 0.25f;
    int y0 = (int)floorf(sy); float fy = sy - (float)y0;
    int y1 = y0 + 1; if (y0 < 0) y0 = 0; if (y1 > 31) y1 = 31;
    float sx = w * 0.5f - 0.25f;
    int x0 = (int)floorf(sx); float fx = sx - (float)x0;
    int x1 = x0 + 1; if (x0 < 0) x0 = 0; if (x1 > 31) x1 = 31;
    const float* p = pos + (size_t)c * 1024;
    float v = (1.f - fy) * ((1.f - fx) * p[y0 * 32 + x0] + fx * p[y0 * 32 + x1])
            + fy * ((1.f - fx) * p[y1 * 32 + x0] + fx * p[y1 * 32 + x1]);
    outp[(size_t)n * Cc + c] = v;
}

// ---------------- pos embed antialiased downsample 32->16, fp32 [256, 256] ----------------
__global__ void pos_down_k(const float* __restrict__ pos, float* __restrict__ outp) {
    int g = blockIdx.x, c = threadIdx.x;
    int gh = g >> 4, gw = g & 15;
    float wy[4], wx[4];
    int iy[4], ix[4];
    float sy = 2.f * gh + 0.5f, sx = 2.f * gw + 0.5f;
    float wsy = 0.f, wsx = 0.f;
    for (int tp = 0; tp < 4; tp++) {
        int i = 2 * gh - 1 + tp;
        float wg = 0.f;
        if (i >= 0 && i < 32) wg = fmaxf(0.f, 1.f - fabsf((float)i - sy) * 0.5f);
        iy[tp] = i < 0 ? 0 : (i > 31 ? 31 : i); wy[tp] = wg; wsy += wg;
        int j = 2 * gw - 1 + tp;
        float wg2 = 0.f;
        if (j >= 0 && j < 32) wg2 = fmaxf(0.f, 1.f - fabsf((float)j - sx) * 0.5f);
        ix[tp] = j < 0 ? 0 : (j > 31 ? 31 : j); wx[tp] = wg2; wsx += wg2;
    }
    const float* p = pos + (size_t)c * 1024;
    float acc = 0.f;
    for (int a = 0; a < 4; a++)
        for (int bq = 0; bq < 4; bq++)
            acc += wy[a] * wx[bq] * p[iy[a] * 32 + ix[bq]];
    outp[(size_t)g * Cc + c] = acc / (wsy * wsx);
}

// ---------------- 4x4 avg pool (fp32 out) ----------------
__global__ void avgpool_k(const float* __restrict__ x, float* __restrict__ xgt) {
    int c = blockIdx.x, b = blockIdx.y, g = threadIdx.x;
    int gh = g >> 4, gw = g & 15;
    const float* xp = x + ((size_t)(b * Cc + c)) * Nn;
    float s = 0.f;
    #pragma unroll
    for (int dh = 0; dh < 4; dh++)
        #pragma unroll
        for (int dw = 0; dw < 4; dw++)
            s += xp[(gh * 4 + dh) * 64 + gw * 4 + dw];
    xgt[((size_t)(b * Cc + c)) * NG + g] = s * (1.f / 16.f);
}

// ---------------- partial mean over tokens, vectorized (uint4 = 8 bf16) ----------------
// grid (P, B), block 256 = 32 c-groups x 8 token-groups; partials [B, P*8, C]
__global__ void mean_part8(const bf* __restrict__ u, float* __restrict__ part,
                           int Ntok, int P) {
    int p = blockIdx.x, b = blockIdx.y;
    int t = threadIdx.x;
    int c0 = (t & 31) * 8;
    int tg = t >> 5;
    int per = Ntok / P / 8;
    float s[8];
    #pragma unroll
    for (int j = 0; j < 8; j++) s[j] = 0.f;
    int nbase = p * (Ntok / P) + tg * per;
    for (int i = 0; i < per; i++) {
        int n = nbase + i;
        uint4 q = *reinterpret_cast<const uint4*>(u + ((size_t)(b * Ntok + n)) * Cc + c0);
        const bf* e = reinterpret_cast<const bf*>(&q);
        #pragma unroll
        for (int j = 0; j < 8; j++) s[j] += b2f(e[j]);
    }
    float* dst = part + ((size_t)(b * P * 8 + p * 8 + tg)) * Cc + c0;
    *reinterpret_cast<float4*>(dst)     = make_float4(s[0], s[1], s[2], s[3]);
    *reinterpret_cast<float4*>(dst + 4) = make_float4(s[4], s[5], s[6], s[7]);
}

// ---------------- layernorm of pooled context -> bf16 ----------------
__global__ void ln_ctx_k(const float* __restrict__ part, int P, float invN,
                         const float* __restrict__ gam, const float* __restrict__ bet,
                         bf* __restrict__ outp) {
    int b = blockIdx.x, c = threadIdx.x;
    float s = 0.f;
    for (int p = 0; p < P; p++) s += part[((size_t)(b * P + p)) * Cc + c];
    float m = s * invN;
    __shared__ float red[Cc];
    __shared__ float s_mu, s_var;
    red[c] = m; __syncthreads();
    for (int off = 128; off; off >>= 1) { if (c < off) red[c] += red[c + off]; __syncthreads(); }
    if (c == 0) s_mu = red[0] * (1.f / Cc);
    __syncthreads();
    float dm = m - s_mu;
    red[c] = dm * dm; __syncthreads();
    for (int off = 128; off; off >>= 1) { if (c < off) red[c] += red[c + off]; __syncthreads(); }
    if (c == 0) s_var = red[0] * (1.f / Cc);
    __syncthreads();
    outp[b * Cc + c] = __float2bfloat16(dm * rsqrtf(s_var + 1e-5f) * gam[c] + bet[c]);
}

// ---------------- bf16 tensor-core segmented GEMM (bf16 A inputs) ----------------
// grid (2, M/128): the two N-blocks of the same M-tile are launch-adjacent -> A hits L2.
// mode 0: out(bf16) = acc+bias (+aux fp32)
// mode 1: out(bf16) = sigmoid(acc+bias)
// mode 2: t=sig; out(bf16) = t*P + (1-t)*Q
// mode 3: t=sig; out(bf16) = P + t*Q
// mode 4: out(f32) = sigmoid(-(acc+bias))
// mode 5: out(f32) = (1-Pf)*sigmoid(acc+bias)*Q
__device__ __forceinline__ uint32_t pk(float lo, float hi) {
    uint32_t r;
    asm("cvt.rn.bf16x2.f32 %0, %1, %2;" : "=r"(r) : "f"(hi), "f"(lo));
    return r;
}

__device__ __forceinline__ void g2r(
    const bf* __restrict__ A0, const bf* __restrict__ A1, const bf* __restrict__ A2,
    int bcast, int tshift, const float* __restrict__ Wm,
    int tile, int m0, int n0, int am, int ah, int wkp, int wnq,
    uint32_t ra[8], uint32_t rw[8]) {
    int k0 = tile * 32;
    int seg = k0 >> 8;
    const bf* p = (seg == 0) ? A0 : ((seg == 1) ? A1 : A2);
    bool bc = (bcast >> seg) & 1;
    int row = bc ? ((m0 + am) >> tshift) : (m0 + am);
    const bf* ap = p + ((size_t)row << 8) + (k0 & 255) + ah;
    uint4 q0 = *reinterpret_cast<const uint4*>(ap);
    uint4 q1 = *reinterpret_cast<const uint4*>(ap + 8);
    ra[0] = q0.x; ra[1] = q0.y; ra[2] = q0.z; ra[3] = q0.w;
    ra[4] = q1.x; ra[5] = q1.y; ra[6] = q1.z; ra[7] = q1.w;
    const float* wp = Wm + ((size_t)(k0 + 2 * wkp) << 8) + n0 + wnq;
    float4 w0 = *reinterpret_cast<const float4*>(wp);
    float4 w1 = *reinterpret_cast<const float4*>(wp + 4);
    float4 w2 = *reinterpret_cast<const float4*>(wp + 256);
    float4 w3 = *reinterpret_cast<const float4*>(wp + 260);
    rw[0] = pk(w0.x, w2.x); rw[1] = pk(w0.y, w2.y);
    rw[2] = pk(w0.z, w2.z); rw[3] = pk(w0.w, w2.w);
    rw[4] = pk(w1.x, w3.x); rw[5] = pk(w1.y, w3.y);
    rw[6] = pk(w1.z, w3.z); rw[7] = pk(w1.w, w3.w);
}

__global__ __launch_bounds__(256) void gemm_k(
    const bf* __restrict__ A0, const bf* __restrict__ A1, const bf* __restrict__ A2,
    int bcast, int nseg, int tshift,
    const float* __restrict__ Wm, const float* __restrict__ bias,
    const float* __restrict__ aux, int tmask,
    const bf* __restrict__ P, const float* __restrict__ Pf, const bf* __restrict__ Q,
    void* __restrict__ outp, int mode) {
    __shared__ uint32_t As[2][128][20];
    __shared__ uint32_t Ws[2][16][136];
    const int t = threadIdx.x;
    const int m0 = blockIdx.y * 128;
    const int n0 = blockIdx.x * 128;
    const int wid = t >> 5, lane = t & 31;
    const int wm = (wid >> 2) * 64;
    const int wn = (wid & 3) * 32;
    const int g = lane >> 2, tig = lane & 3;
    const int am = t >> 1;
    const int ah = (t & 1) * 16;
    const int wkp = t >> 4;
    const int wnq = (t & 15) * 8;

    float acc[4][4][4];
    #pragma unroll
    for (int mt = 0; mt < 4; mt++)
        #pragma unroll
        for (int nt = 0; nt < 4; nt++)
            #pragma unroll
            for (int cq = 0; cq < 4; cq++) acc[mt][nt][cq] = 0.f;

    const int T = nseg << 3;
    uint32_t ra[8], rw[8];

    g2r(A0, A1, A2, bcast, tshift, Wm, 0, m0, n0, am, ah, wkp, wnq, ra, rw);
    {
        int kp0 = ah >> 1;
        *reinterpret_cast<uint4*>(&As[0][am][kp0])     = make_uint4(ra[0], ra[1], ra[2], ra[3]);
        *reinterpret_cast<uint4*>(&As[0][am][kp0 + 4]) = make_uint4(ra[4], ra[5], ra[6], ra[7]);
        *reinterpret_cast<uint4*>(&Ws[0][wkp][wnq])     = make_uint4(rw[0], rw[1], rw[2], rw[3]);
        *reinterpret_cast<uint4*>(&Ws[0][wkp][wnq + 4]) = make_uint4(rw[4], rw[5], rw[6], rw[7]);
    }
    __syncthreads();

    for (int tt = 0; tt < T; tt++) {
        if (tt + 1 < T)
            g2r(A0, A1, A2, bcast, tshift, Wm, tt + 1, m0, n0, am, ah, wkp, wnq, ra, rw);
        const int buf = tt & 1;
        #pragma unroll
        for (int kp = 0; kp < 16; kp += 8) {
            uint32_t af[4][4], bfr[4][2];
            #pragma unroll
            for (int mt = 0; mt < 4; mt++) {
                int r = wm + mt * 16 + g;
                af[mt][0] = As[buf][r][kp + tig];
                af[mt][1] = As[buf][r + 8][kp + tig];
                af[mt][2] = As[buf][r][kp + tig + 4];
                af[mt][3] = As[buf][r + 8][kp + tig + 4];
            }
            #pragma unroll
            for (int nt = 0; nt < 4; nt++) {
                bfr[nt][0] = Ws[buf][kp + tig][wn + nt * 8 + g];
                bfr[nt][1] = Ws[buf][kp + tig + 4][wn + nt * 8 + g];
            }
            #pragma unroll
            for (int mt = 0; mt < 4; mt++)
                #pragma unroll
                for (int nt = 0; nt < 4; nt++) {
                    asm volatile(
                        "mma.sync.aligned.m16n8k16.row.col.f32.bf16.bf16.f32 "
                        "{%0,%1,%2,%3}, {%4,%5,%6,%7}, {%8,%9}, {%0,%1,%2,%3};"
                        : "+f"(acc[mt][nt][0]), "+f"(acc[mt][nt][1]),
                          "+f"(acc[mt][nt][2]), "+f"(acc[mt][nt][3])
                        : "r"(af[mt][0]), "r"(af[mt][1]), "r"(af[mt][2]), "r"(af[mt][3]),
                          "r"(bfr[nt][0]), "r"(bfr[nt][1]));
                }
        }
        if (tt + 1 < T) {
            const int nb = (tt + 1) & 1;
            int kp0 = ah >> 1;
            *reinterpret_cast<uint4*>(&As[nb][am][kp0])     = make_uint4(ra[0], ra[1], ra[2], ra[3]);
            *reinterpret_cast<uint4*>(&As[nb][am][kp0 + 4]) = make_uint4(ra[4], ra[5], ra[6], ra[7]);
            *reinterpret_cast<uint4*>(&Ws[nb][wkp][wnq])     = make_uint4(rw[0], rw[1], rw[2], rw[3]);
            *reinterpret_cast<uint4*>(&Ws[nb][wkp][wnq + 4]) = make_uint4(rw[4], rw[5], rw[6], rw[7]);
            __syncthreads();
        }
    }

    bf* outb = (bf*)outp;
    float* outf = (float*)outp;
    #pragma unroll
    for (int mt = 0; mt < 4; mt++) {
        #pragma unroll
        for (int nt = 0; nt < 4; nt++) {
            int r = m0 + wm + mt * 16 + g;
            int cN = n0 + wn + nt * 8 + 2 * tig;
            float vv[4];
            size_t idx0[4];
            #pragma unroll
            for (int cq = 0; cq < 4; cq++) {
                int m = r + (cq >> 1) * 8;
                int n = cN + (cq & 1);
                size_t idx = ((size_t)m << 8) + n;
                idx0[cq] = idx;
                float v = acc[mt][nt][cq] + bias[n];
                if (mode == 0) {
                    if (aux) v += aux[((size_t)(m & tmask) << 8) + n];
                } else if (mode == 1) {
                    v = 1.f / (1.f + expf(-v));
                } else if (mode == 4) {
                    v = 1.f / (1.f + expf(v));
                } else if (mode == 5) {
                    float sg = 1.f / (1.f + expf(-v));
                    v = (1.f - Pf[idx]) * sg * b2f(Q[idx]);
                } else {
                    float sg = 1.f / (1.f + expf(-v));
                    v = (mode == 2) ? (sg * b2f(P[idx]) + (1.f - sg) * b2f(Q[idx]))
                                    : (b2f(P[idx]) + sg * b2f(Q[idx]));
                }
                vv[cq] = v;
            }
            if (mode >= 4) {
                #pragma unroll
                for (int cq = 0; cq < 4; cq++) outf[idx0[cq]] = vv[cq];
            } else {
                *reinterpret_cast<uint32_t*>(outb + idx0[0]) = pk(vv[0], vv[1]);
                *reinterpret_cast<uint32_t*>(outb + idx0[2]) = pk(vv[2], vv[3]);
            }
        }
    }
}

// ---------------- fused bidirectional chunk-aggregate scan (phase 1) ----------------
__global__ void scan_p1_bi(const float* __restrict__ A, const float* __restrict__ Bv,
                           float* __restrict__ Ach, float* __restrict__ Bchf,
                           float* __restrict__ Bchb) {
    int k = blockIdx.x, b = blockIdx.y, c = threadIdx.x;
    const int clen = Nn / NCH;
    float Pp = 1.f, Bf = 0.f, Bbk = 0.f;
    for (int i = 0; i < clen; i++) {
        int n = k * clen + i;
        size_t idx = ((size_t)(b * Nn + n)) * Cc + c;
        float a = A[idx], bb = Bv[idx];
        Bf = a * Bf + bb;
        Bbk = fmaf(bb, Pp, Bbk);
        Pp *= a;
    }
    Ach[((size_t)(b * NCH + k)) * Cc + c] = Pp;
    Bchf[((size_t)(b * NCH + k)) * Cc + c] = Bf;
    Bchb[((size_t)(b * NCH + (NCH - 1 - k))) * Cc + c] = Bbk;
}

// ---------------- phase 2: inter-chunk prefix for both directions ----------------
__global__ void scan_p2_bi(const float* __restrict__ Ach, const float* __restrict__ Bchf,
                           const float* __restrict__ Bchb, float* __restrict__ Sinf,
                           float* __restrict__ Sinb) {
    int b = blockIdx.x, c = threadIdx.x;
    float sf = 0.f, sb = 0.f;
    for (int k = 0; k < NCH; k++) {
        size_t idx = ((size_t)(b * NCH + k)) * Cc + c;
        Sinf[idx] = sf;
        sf = Ach[idx] * sf + Bchf[idx];
        size_t idxr = ((size_t)(b * NCH + (NCH - 1 - k))) * Cc + c;
        Sinb[idx] = sb;
        sb = Ach[idxr] * sb + Bchb[idx];
    }
}

// ---------------- phase 3 fused: fwd + bwd intra-chunk scan in one kernel ----------------
// block owns natural chunk k. fwd state Sinf[k]; bwd state Sinb[NCH-1-k]
// (bwd-order chunk index of natural chunk k). Second (descending) pass hits L2.
__global__ void scan_p3_bi(const float* __restrict__ A, const float* __restrict__ Bv,
                           const bf* __restrict__ O, const bf* __restrict__ u,
                           const float* __restrict__ Sinf, const float* __restrict__ Sinb,
                           bf* __restrict__ yf, bf* __restrict__ yb) {
    int k = blockIdx.x, b = blockIdx.y, c = threadIdx.x;
    const int clen = Nn / NCH;
    size_t base = ((size_t)(b * Nn + k * clen)) * Cc + c;
    float s = Sinf[((size_t)(b * NCH + k)) * Cc + c];
    for (int i = 0; i < clen; i++) {
        size_t idx = base + (size_t)i * Cc;
        float a = A[idx];
        s = a * s + Bv[idx];
        float o = b2f(O[idx]);
        yf[idx] = __float2bfloat16(o * s + (1.f - o) * b2f(u[idx]));
    }
    s = Sinb[((size_t)(b * NCH + (NCH - 1 - k))) * Cc + c];
    for (int i = clen - 1; i >= 0; i--) {
        size_t idx = base + (size_t)i * Cc;
        float a = A[idx];
        s = a * s + Bv[idx];
        float o = b2f(O[idx]);
        yb[idx] = __float2bfloat16(o * s + (1.f - o) * b2f(u[idx]));
    }
}

// ---------------- simple forward scan (global branch, bf16 o/u/y) ----------------
__global__ void scan_fwd_simple(const float* __restrict__ A, const float* __restrict__ Bv,
                                const bf* __restrict__ O, const bf* __restrict__ u,
                                bf* __restrict__ y, int Ntok) {
    int b = blockIdx.x, c = threadIdx.x;
    float s = 0.f;
    for (int n = 0; n < Ntok; n++) {
        size_t idx = ((size_t)(b * Ntok + n)) * Cc + c;
        float a = A[idx];
        s = a * s + Bv[idx];
        float o = b2f(O[idx]);
        y[idx] = __float2bfloat16(o * s + (1.f - o) * b2f(u[idx]));
    }
}

// ---------------- bilinear upsample 16->64 (bf16 in/out) ----------------
__global__ void upsample_g(const bf* __restrict__ yg, bf* __restrict__ outp) {
    int n = blockIdx.x, b = blockIdx.y, c = threadIdx.x;
    int h = n >> 6, w = n & 63;
    float sy = h * 0.25f - 0.375f;
    int y0 = (int)floorf(sy); float fy = sy - (float)y0;
    int y1 = y0 + 1; if (y0 < 0) y0 = 0; if (y1 > 15) y1 = 15;
    float sx = w * 0.25f - 0.375f;
    int x0 = (int)floorf(sx); float fx = sx - (float)x0;
    int x1 = x0 + 1; if (x0 < 0) x0 = 0; if (x1 > 15) x1 = 15;
    const bf* base = yg + ((size_t)b * NG) * Cc + c;
    float v00 = b2f(base[(size_t)(y0 * 16 + x0) * Cc]);
    float v01 = b2f(base[(size_t)(y0 * 16 + x1) * Cc]);
    float v10 = b2f(base[(size_t)(y1 * 16 + x0) * Cc]);
    float v11 = b2f(base[(size_t)(y1 * 16 + x1) * Cc]);
    float v = (1.f - fy) * ((1.f - fx) * v00 + fx * v01) + fy * ((1.f - fx) * v10 + fx * v11);
    outp[((size_t)(b * Nn + n)) * Cc + c] = __float2bfloat16(v);
}

// ---------------- 3x3 depthwise conv (bf16 out) ----------------
__global__ void dwconv_k(const float* __restrict__ x, const float* __restrict__ wdw,
                         const float* __restrict__ bdw, bf* __restrict__ vmap) {
    int c = blockIdx.y, b = blockIdx.z;
    int n = blockIdx.x * 256 + threadIdx.x;
    int h = n >> 6, w = n & 63;
    const float* xp = x + ((size_t)(b * Cc + c)) * Nn;
    const float* kp = wdw + c * 9;
    float s = bdw[c];
    #pragma unroll
    for (int kh = 0; kh < 3; kh++) {
        int hh = h + kh - 1;
        if (hh < 0 || hh > 63) continue;
        #pragma unroll
        for (int kw = 0; kw < 3; kw++) {
            int ww2 = w + kw - 1;
            if (ww2 < 0 || ww2 > 63) continue;
            s += xp[hh * 64 + ww2] * kp[kh * 3 + kw];
        }
    }
    vmap[((size_t)(b * Cc + c)) * Nn + n] = __float2bfloat16(s);
}

// ---------------- host ----------------
static inline void gemm(const bf* A0, const bf* A1, const bf* A2, int bcast, int nseg,
                        int tshift, const float* Wm, const float* bias, const float* aux,
                        int tmask, const bf* P, const float* Pf, const bf* Q,
                        void* outp, int M, int mode) {
    gemm_k<<<dim3(2, M / 128), 256>>>(A0, A1, A2, bcast, nseg, tshift, Wm, bias, aux, tmask,
                                      P, Pf, Q, outp, mode);
}

#define SYMF(p, s) float* p; cudaGetSymbolAddress((void**)&p, s)
#define SYMB(p, s) bf* p;    cudaGetSymbolAddress((void**)&p, s)

extern "C" void kernel_launch(void* const* d_in, const int* in_sizes, int n_in,
                              void* d_out, int out_size) {
    const float* x    = (const float*)d_in[0];
    const float* Wt   = (const float*)d_in[1];
    const float* bt   = (const float*)d_in[2];
    const float* pf   = (const float*)d_in[3];
    const float* pg   = (const float*)d_in[4];
    const float* lng  = (const float*)d_in[5];
    const float* lnb  = (const float*)d_in[6];
    const float* Wf   = (const float*)d_in[7];
    const float* bfb  = (const float*)d_in[8];
    const float* Wwm  = (const float*)d_in[9];
    const float* bw   = (const float*)d_in[10];
    const float* Wo   = (const float*)d_in[11];
    const float* bo   = (const float*)d_in[12];
    const float* Wr   = (const float*)d_in[13];
    const float* br   = (const float*)d_in[14];
    const float* Wgi  = (const float*)d_in[15];
    const float* bgi  = (const float*)d_in[16];
    const float* dww  = (const float*)d_in[17];
    const float* dwb  = (const float*)d_in[18];
    const float* Wl   = (const float*)d_in[19];
    const float* bl   = (const float*)d_in[20];
    const float* Wlf  = (const float*)d_in[21];
    const float* blf  = (const float*)d_in[22];
    const float* Wout = (const float*)d_in[23];
    const float* bout = (const float*)d_in[24];
    float* outp = (float*)d_out;

    SYMB(xs, g_xs);   SYMB(u, g_u);     SYMF(a_, g_a);    SYMF(b_, g_b);    SYMB(o_, g_o);
    SYMB(yf, g_yf);   SYMB(yb, g_yb);   SYMB(y, g_y);     SYMB(ygs, g_ygs); SYMB(z, g_z);
    SYMB(vmap, g_vmap); SYMB(vt, g_vt); SYMB(v, g_v);     SYMB(tmp, g_tmp); SYMB(uo, g_uo);
    SYMF(posf, g_posf); SYMF(posg, g_posg); SYMF(mpart, g_mpart);
    SYMB(cctx, g_cctx); SYMB(cctx2, g_cctx2);
    SYMF(Ach, g_Ach); SYMF(Bchf, g_Bchf); SYMF(Bchb, g_Bchb);
    SYMF(Sinf, g_Sinf); SYMF(Sinb, g_Sinb);
    SYMF(xgt, g_xgt); SYMB(xgs, g_xgs); SYMB(ug, g_ug);
    SYMF(a2, g_a2);   SYMF(b2, g_b2);   SYMB(o2, g_o2);   SYMB(yg, g_yg);

    dim3 tb(32, 8);

    // ---- fine branch ----
    trans_cn_nc<<<dim3(128, 8, Bb), tb>>>(x, xs, Nn);
    pos_up_k<<<Nn, Cc>>>(pf, posf);
    gemm(xs, 0, 0, 0, 1, 12, Wt, bt, posf, 4095, 0, 0, 0, u, Bb * Nn, 0);

    mean_part8<<<dim3(32, Bb), 256>>>(u, mpart, Nn, 32);
    ln_ctx_k<<<Bb, Cc>>>(mpart, 256, 1.f / Nn, lng, lnb, cctx);

    // gates fused into GEMM epilogues (a f32 -> o bf16 -> b f32 reads a)
    gemm(u, cctx, 0, 2, 2, 12, Wf, bfb, 0, 0, 0, 0, 0, a_, Bb * Nn, 4);
    gemm(u, cctx, 0, 2, 2, 12, Wo, bo, 0, 0, 0, 0, 0, o_, Bb * Nn, 1);
    gemm(u, cctx, 0, 2, 2, 12, Wwm, bw, 0, 0, 0, a_, u, b_, Bb * Nn, 5);

    scan_p1_bi<<<dim3(NCH, Bb), Cc>>>(a_, b_, Ach, Bchf, Bchb);
    scan_p2_bi<<<Bb, Cc>>>(Ach, Bchf, Bchb, Sinf, Sinb);
    scan_p3_bi<<<dim3(NCH, Bb), Cc>>>(a_, b_, o_, u, Sinf, Sinb, yf, yb);

    // rho GEMM + blend fused
    gemm(u, yf, yb, 0, 3, 12, Wr, br, 0, 0, yf, 0, yb, y, Bb * Nn, 2);

    // ---- global branch ----
    avgpool_k<<<dim3(Cc, Bb), 256>>>(x, xgt);
    trans_cn_nc<<<dim3(8, 8, Bb), tb>>>(xgt, xgs, NG);
    pos_down_k<<<NG, Cc>>>(pg, posg);
    gemm(xgs, 0, 0, 0, 1, 8, Wt, bt, posg, 255, 0, 0, 0, ug, Bb * NG, 0);

    mean_part8<<<dim3(8, Bb), 256>>>(ug, mpart, NG, 8);
    ln_ctx_k<<<Bb, Cc>>>(mpart, 64, 1.f / NG, lng, lnb, cctx2);

    gemm(ug, cctx2, 0, 2, 2, 8, Wf, bfb, 0, 0, 0, 0, 0, a2, Bb * NG, 4);
    gemm(ug, cctx2, 0, 2, 2, 8, Wo, bo, 0, 0, 0, 0, 0, o2, Bb * NG, 1);
    gemm(ug, cctx2, 0, 2, 2, 8, Wwm, bw, 0, 0, 0, a2, ug, b2, Bb * NG, 5);
    scan_fwd_simple<<<Bb, Cc>>>(a2, b2, o2, ug, yg, NG);
    upsample_g<<<dim3(Nn, Bb), Cc>>>(yg, ygs);

    // lam GEMM + blend fused: z = y + sig(..)*ygs
    gemm(y, ygs, u, 0, 3, 12, Wgi, bgi, 0, 0, y, 0, ygs, z, Bb * Nn, 3);

    // ---- local depthwise branch ----
    dwconv_k<<<dim3(16, Cc, Bb), 256>>>(x, dww, dwb, vmap);
    trans_cn_nc_bf<<<dim3(128, 8, Bb), tb>>>(vmap, vt, Nn);
    gemm(vt, 0, 0, 0, 1, 12, Wl, bl, 0, 0, 0, 0, 0, v, Bb * Nn, 0);
    // eta GEMM + blend fused
    gemm(v, z, 0, 0, 2, 12, Wlf, blf, 0, 0, v, 0, z, uo, Bb * Nn, 2);

    // ---- output proj + residual ----
    gemm(uo, 0, 0, 0, 1, 12, Wout, bout, 0, 0, 0, 0, 0, tmp, Bb * Nn, 0);
    trans_add_k<<<dim3(128, 8, Bb), tb>>>(tmp, x, outp);
}

// round 9
// speedup vs baseline: 1.1808x; 1.1808x over previous
#include <cuda_runtime.h>
#include <cuda_bf16.h>
#include <stdint.h>
#include <math.h>

typedef __nv_bfloat16 bf;

#define Bb 8
#define Cc 256
#define Nn 4096
#define NG 256
#define NCH 64
#define BNC (Bb*Nn*Cc)
#define BGC (Bb*NG*Cc)

// ---------------- scratch (static __device__ — no allocation) ----------------
__device__ bf    g_xs[BNC];
__device__ bf    g_u[BNC];
__device__ float g_a[BNC];
__device__ float g_b[BNC];
__device__ bf    g_o[BNC];
__device__ bf    g_yf[BNC];
__device__ bf    g_yb[BNC];
__device__ bf    g_y[BNC];
__device__ bf    g_ygs[BNC];
__device__ bf    g_z[BNC];
__device__ bf    g_vmap[BNC];
__device__ bf    g_vt[BNC];
__device__ bf    g_v[BNC];
__device__ bf    g_tmp[BNC];
__device__ bf    g_uo[BNC];
__device__ float g_posf[Nn*Cc];
__device__ float g_posg[NG*Cc];
__device__ float g_mpart[Bb*256*Cc];
__device__ bf    g_cctx[Bb*Cc];
__device__ bf    g_cctx2[Bb*Cc];
__device__ float g_Ach[Bb*NCH*Cc];
__device__ float g_Bchf[Bb*NCH*Cc];
__device__ float g_Bchb[Bb*NCH*Cc];
__device__ float g_Sinf[Bb*NCH*Cc];
__device__ float g_Sinb[Bb*NCH*Cc];
__device__ float g_xgt[BGC];
__device__ bf    g_xgs[BGC];
__device__ bf    g_ug[BGC];
__device__ float g_a2[BGC];
__device__ float g_b2[BGC];
__device__ bf    g_o2[BGC];
__device__ bf    g_yg[BGC];

__device__ __forceinline__ float b2f(bf x) { return __bfloat162float(x); }

// ---------------- transpose [B,C,Ntok] f32 -> [B,Ntok,C] bf16 ----------------
__global__ void trans_cn_nc(const float* __restrict__ in, bf* __restrict__ outp, int Ntok) {
    __shared__ float tile[32][33];
    int b = blockIdx.z;
    int n0 = blockIdx.x * 32, c0 = blockIdx.y * 32;
    int tx = threadIdx.x, ty = threadIdx.y;
    for (int i = ty; i < 32; i += 8)
        tile[i][tx] = in[((size_t)(b * Cc + c0 + i)) * Ntok + n0 + tx];
    __syncthreads();
    for (int i = ty; i < 32; i += 8)
        outp[((size_t)(b * Ntok + n0 + i)) * Cc + c0 + tx] = __float2bfloat16(tile[tx][i]);
}

// ---------------- transpose [B,C,Ntok] bf16 -> [B,Ntok,C] bf16 ----------------
__global__ void trans_cn_nc_bf(const bf* __restrict__ in, bf* __restrict__ outp, int Ntok) {
    __shared__ bf tile[32][33];
    int b = blockIdx.z;
    int n0 = blockIdx.x * 32, c0 = blockIdx.y * 32;
    int tx = threadIdx.x, ty = threadIdx.y;
    for (int i = ty; i < 32; i += 8)
        tile[i][tx] = in[((size_t)(b * Cc + c0 + i)) * Ntok + n0 + tx];
    __syncthreads();
    for (int i = ty; i < 32; i += 8)
        outp[((size_t)(b * Ntok + n0 + i)) * Cc + c0 + tx] = tile[tx][i];
}

// ---------------- transpose-add: out[b,c,n] = x[b,c,n] + proj_bf16[b,n,c] ----------------
__global__ void trans_add_k(const bf* __restrict__ proj, const float* __restrict__ x,
                            float* __restrict__ outp) {
    __shared__ float tile[32][33];
    int b = blockIdx.z;
    int n0 = blockIdx.x * 32, c0 = blockIdx.y * 32;
    int tx = threadIdx.x, ty = threadIdx.y;
    for (int i = ty; i < 32; i += 8)
        tile[i][tx] = b2f(proj[((size_t)(b * Nn + n0 + i)) * Cc + c0 + tx]);
    __syncthreads();
    for (int i = ty; i < 32; i += 8) {
        size_t idx = ((size_t)(b * Cc + c0 + i)) * Nn + n0 + tx;
        outp[idx] = x[idx] + tile[tx][i];
    }
}

// ---------------- pos embed upsample 32->64, out fp32 [4096, 256] ----------------
__global__ void pos_up_k(const float* __restrict__ pos, float* __restrict__ outp) {
    int n = blockIdx.x, c = threadIdx.x;
    int h = n >> 6, w = n & 63;
    float sy = h * 0.5f - 0.25f;
    int y0 = (int)floorf(sy); float fy = sy - (float)y0;
    int y1 = y0 + 1; if (y0 < 0) y0 = 0; if (y1 > 31) y1 = 31;
    float sx = w * 0.5f - 0.25f;
    int x0 = (int)floorf(sx); float fx = sx - (float)x0;
    int x1 = x0 + 1; if (x0 < 0) x0 = 0; if (x1 > 31) x1 = 31;
    const float* p = pos + (size_t)c * 1024;
    float v = (1.f - fy) * ((1.f - fx) * p[y0 * 32 + x0] + fx * p[y0 * 32 + x1])
            + fy * ((1.f - fx) * p[y1 * 32 + x0] + fx * p[y1 * 32 + x1]);
    outp[(size_t)n * Cc + c] = v;
}

// ---------------- pos embed antialiased downsample 32->16, fp32 [256, 256] ----------------
__global__ void pos_down_k(const float* __restrict__ pos, float* __restrict__ outp) {
    int g = blockIdx.x, c = threadIdx.x;
    int gh = g >> 4, gw = g & 15;
    float wy[4], wx[4];
    int iy[4], ix[4];
    float sy = 2.f * gh + 0.5f, sx = 2.f * gw + 0.5f;
    float wsy = 0.f, wsx = 0.f;
    for (int tp = 0; tp < 4; tp++) {
        int i = 2 * gh - 1 + tp;
        float wg = 0.f;
        if (i >= 0 && i < 32) wg = fmaxf(0.f, 1.f - fabsf((float)i - sy) * 0.5f);
        iy[tp] = i < 0 ? 0 : (i > 31 ? 31 : i); wy[tp] = wg; wsy += wg;
        int j = 2 * gw - 1 + tp;
        float wg2 = 0.f;
        if (j >= 0 && j < 32) wg2 = fmaxf(0.f, 1.f - fabsf((float)j - sx) * 0.5f);
        ix[tp] = j < 0 ? 0 : (j > 31 ? 31 : j); wx[tp] = wg2; wsx += wg2;
    }
    const float* p = pos + (size_t)c * 1024;
    float acc = 0.f;
    for (int a = 0; a < 4; a++)
        for (int bq = 0; bq < 4; bq++)
            acc += wy[a] * wx[bq] * p[iy[a] * 32 + ix[bq]];
    outp[(size_t)g * Cc + c] = acc / (wsy * wsx);
}

// ---------------- 4x4 avg pool (fp32 out) ----------------
__global__ void avgpool_k(const float* __restrict__ x, float* __restrict__ xgt) {
    int c = blockIdx.x, b = blockIdx.y, g = threadIdx.x;
    int gh = g >> 4, gw = g & 15;
    const float* xp = x + ((size_t)(b * Cc + c)) * Nn;
    float s = 0.f;
    #pragma unroll
    for (int dh = 0; dh < 4; dh++)
        #pragma unroll
        for (int dw = 0; dw < 4; dw++)
            s += xp[(gh * 4 + dh) * 64 + gw * 4 + dw];
    xgt[((size_t)(b * Cc + c)) * NG + g] = s * (1.f / 16.f);
}

// ---------------- partial mean over tokens, vectorized (uint4 = 8 bf16) ----------------
__global__ void mean_part8(const bf* __restrict__ u, float* __restrict__ part,
                           int Ntok, int P) {
    int p = blockIdx.x, b = blockIdx.y;
    int t = threadIdx.x;
    int c0 = (t & 31) * 8;
    int tg = t >> 5;
    int per = Ntok / P / 8;
    float s[8];
    #pragma unroll
    for (int j = 0; j < 8; j++) s[j] = 0.f;
    int nbase = p * (Ntok / P) + tg * per;
    for (int i = 0; i < per; i++) {
        int n = nbase + i;
        uint4 q = *reinterpret_cast<const uint4*>(u + ((size_t)(b * Ntok + n)) * Cc + c0);
        const bf* e = reinterpret_cast<const bf*>(&q);
        #pragma unroll
        for (int j = 0; j < 8; j++) s[j] += b2f(e[j]);
    }
    float* dst = part + ((size_t)(b * P * 8 + p * 8 + tg)) * Cc + c0;
    *reinterpret_cast<float4*>(dst)     = make_float4(s[0], s[1], s[2], s[3]);
    *reinterpret_cast<float4*>(dst + 4) = make_float4(s[4], s[5], s[6], s[7]);
}

// ---------------- layernorm of pooled context -> bf16 ----------------
__global__ void ln_ctx_k(const float* __restrict__ part, int P, float invN,
                         const float* __restrict__ gam, const float* __restrict__ bet,
                         bf* __restrict__ outp) {
    int b = blockIdx.x, c = threadIdx.x;
    float s = 0.f;
    for (int p = 0; p < P; p++) s += part[((size_t)(b * P + p)) * Cc + c];
    float m = s * invN;
    __shared__ float red[Cc];
    __shared__ float s_mu, s_var;
    red[c] = m; __syncthreads();
    for (int off = 128; off; off >>= 1) { if (c < off) red[c] += red[c + off]; __syncthreads(); }
    if (c == 0) s_mu = red[0] * (1.f / Cc);
    __syncthreads();
    float dm = m - s_mu;
    red[c] = dm * dm; __syncthreads();
    for (int off = 128; off; off >>= 1) { if (c < off) red[c] += red[c + off]; __syncthreads(); }
    if (c == 0) s_var = red[0] * (1.f / Cc);
    __syncthreads();
    outp[b * Cc + c] = __float2bfloat16(dm * rsqrtf(s_var + 1e-5f) * gam[c] + bet[c]);
}

// ---------------- bf16 tensor-core segmented GEMM (bf16 A inputs) ----------------
// grid (M/128, 2) — R7-validated launch order.
// mode 0: out(bf16) = acc+bias (+aux fp32)
// mode 1: out(bf16) = sigmoid(acc+bias)
// mode 2: t=sig; out(bf16) = t*P + (1-t)*Q
// mode 3: t=sig; out(bf16) = P + t*Q
// mode 4: out(f32) = sigmoid(-(acc+bias))
// mode 5: out(f32) = (1-Pf)*sigmoid(acc+bias)*Q
__device__ __forceinline__ uint32_t pk(float lo, float hi) {
    uint32_t r;
    asm("cvt.rn.bf16x2.f32 %0, %1, %2;" : "=r"(r) : "f"(hi), "f"(lo));
    return r;
}

__device__ __forceinline__ void g2r(
    const bf* __restrict__ A0, const bf* __restrict__ A1, const bf* __restrict__ A2,
    int bcast, int tshift, const float* __restrict__ Wm,
    int tile, int m0, int n0, int am, int ah, int wkp, int wnq,
    uint32_t ra[8], uint32_t rw[8]) {
    int k0 = tile * 32;
    int seg = k0 >> 8;
    const bf* p = (seg == 0) ? A0 : ((seg == 1) ? A1 : A2);
    bool bc = (bcast >> seg) & 1;
    int row = bc ? ((m0 + am) >> tshift) : (m0 + am);
    const bf* ap = p + ((size_t)row << 8) + (k0 & 255) + ah;
    uint4 q0 = *reinterpret_cast<const uint4*>(ap);
    uint4 q1 = *reinterpret_cast<const uint4*>(ap + 8);
    ra[0] = q0.x; ra[1] = q0.y; ra[2] = q0.z; ra[3] = q0.w;
    ra[4] = q1.x; ra[5] = q1.y; ra[6] = q1.z; ra[7] = q1.w;
    const float* wp = Wm + ((size_t)(k0 + 2 * wkp) << 8) + n0 + wnq;
    float4 w0 = *reinterpret_cast<const float4*>(wp);
    float4 w1 = *reinterpret_cast<const float4*>(wp + 4);
    float4 w2 = *reinterpret_cast<const float4*>(wp + 256);
    float4 w3 = *reinterpret_cast<const float4*>(wp + 260);
    rw[0] = pk(w0.x, w2.x); rw[1] = pk(w0.y, w2.y);
    rw[2] = pk(w0.z, w2.z); rw[3] = pk(w0.w, w2.w);
    rw[4] = pk(w1.x, w3.x); rw[5] = pk(w1.y, w3.y);
    rw[6] = pk(w1.z, w3.z); rw[7] = pk(w1.w, w3.w);
}

__global__ __launch_bounds__(256) void gemm_k(
    const bf* __restrict__ A0, const bf* __restrict__ A1, const bf* __restrict__ A2,
    int bcast, int nseg, int tshift,
    const float* __restrict__ Wm, const float* __restrict__ bias,
    const float* __restrict__ aux, int tmask,
    const bf* __restrict__ P, const float* __restrict__ Pf, const bf* __restrict__ Q,
    void* __restrict__ outp, int mode) {
    __shared__ uint32_t As[2][128][20];
    __shared__ uint32_t Ws[2][16][136];
    const int t = threadIdx.x;
    const int m0 = blockIdx.x * 128;
    const int n0 = blockIdx.y * 128;
    const int wid = t >> 5, lane = t & 31;
    const int wm = (wid >> 2) * 64;
    const int wn = (wid & 3) * 32;
    const int g = lane >> 2, tig = lane & 3;
    const int am = t >> 1;
    const int ah = (t & 1) * 16;
    const int wkp = t >> 4;
    const int wnq = (t & 15) * 8;

    float acc[4][4][4];
    #pragma unroll
    for (int mt = 0; mt < 4; mt++)
        #pragma unroll
        for (int nt = 0; nt < 4; nt++)
            #pragma unroll
            for (int cq = 0; cq < 4; cq++) acc[mt][nt][cq] = 0.f;

    const int T = nseg << 3;
    uint32_t ra[8], rw[8];

    g2r(A0, A1, A2, bcast, tshift, Wm, 0, m0, n0, am, ah, wkp, wnq, ra, rw);
    {
        int kp0 = ah >> 1;
        *reinterpret_cast<uint4*>(&As[0][am][kp0])     = make_uint4(ra[0], ra[1], ra[2], ra[3]);
        *reinterpret_cast<uint4*>(&As[0][am][kp0 + 4]) = make_uint4(ra[4], ra[5], ra[6], ra[7]);
        *reinterpret_cast<uint4*>(&Ws[0][wkp][wnq])     = make_uint4(rw[0], rw[1], rw[2], rw[3]);
        *reinterpret_cast<uint4*>(&Ws[0][wkp][wnq + 4]) = make_uint4(rw[4], rw[5], rw[6], rw[7]);
    }
    __syncthreads();

    for (int tt = 0; tt < T; tt++) {
        if (tt + 1 < T)
            g2r(A0, A1, A2, bcast, tshift, Wm, tt + 1, m0, n0, am, ah, wkp, wnq, ra, rw);
        const int buf = tt & 1;
        #pragma unroll
        for (int kp = 0; kp < 16; kp += 8) {
            uint32_t af[4][4], bfr[4][2];
            #pragma unroll
            for (int mt = 0; mt < 4; mt++) {
                int r = wm + mt * 16 + g;
                af[mt][0] = As[buf][r][kp + tig];
                af[mt][1] = As[buf][r + 8][kp + tig];
                af[mt][2] = As[buf][r][kp + tig + 4];
                af[mt][3] = As[buf][r + 8][kp + tig + 4];
            }
            #pragma unroll
            for (int nt = 0; nt < 4; nt++) {
                bfr[nt][0] = Ws[buf][kp + tig][wn + nt * 8 + g];
                bfr[nt][1] = Ws[buf][kp + tig + 4][wn + nt * 8 + g];
            }
            #pragma unroll
            for (int mt = 0; mt < 4; mt++)
                #pragma unroll
                for (int nt = 0; nt < 4; nt++) {
                    asm volatile(
                        "mma.sync.aligned.m16n8k16.row.col.f32.bf16.bf16.f32 "
                        "{%0,%1,%2,%3}, {%4,%5,%6,%7}, {%8,%9}, {%0,%1,%2,%3};"
                        : "+f"(acc[mt][nt][0]), "+f"(acc[mt][nt][1]),
                          "+f"(acc[mt][nt][2]), "+f"(acc[mt][nt][3])
                        : "r"(af[mt][0]), "r"(af[mt][1]), "r"(af[mt][2]), "r"(af[mt][3]),
                          "r"(bfr[nt][0]), "r"(bfr[nt][1]));
                }
        }
        if (tt + 1 < T) {
            const int nb = (tt + 1) & 1;
            int kp0 = ah >> 1;
            *reinterpret_cast<uint4*>(&As[nb][am][kp0])     = make_uint4(ra[0], ra[1], ra[2], ra[3]);
            *reinterpret_cast<uint4*>(&As[nb][am][kp0 + 4]) = make_uint4(ra[4], ra[5], ra[6], ra[7]);
            *reinterpret_cast<uint4*>(&Ws[nb][wkp][wnq])     = make_uint4(rw[0], rw[1], rw[2], rw[3]);
            *reinterpret_cast<uint4*>(&Ws[nb][wkp][wnq + 4]) = make_uint4(rw[4], rw[5], rw[6], rw[7]);
            __syncthreads();
        }
    }

    bf* outb = (bf*)outp;
    float* outf = (float*)outp;
    #pragma unroll
    for (int mt = 0; mt < 4; mt++) {
        #pragma unroll
        for (int nt = 0; nt < 4; nt++) {
            int r = m0 + wm + mt * 16 + g;
            int cN = n0 + wn + nt * 8 + 2 * tig;
            float vv[4];
            size_t idx0[4];
            #pragma unroll
            for (int cq = 0; cq < 4; cq++) {
                int m = r + (cq >> 1) * 8;
                int n = cN + (cq & 1);
                size_t idx = ((size_t)m << 8) + n;
                idx0[cq] = idx;
                float v = acc[mt][nt][cq] + bias[n];
                if (mode == 0) {
                    if (aux) v += aux[((size_t)(m & tmask) << 8) + n];
                } else if (mode == 1) {
                    v = 1.f / (1.f + expf(-v));
                } else if (mode == 4) {
                    v = 1.f / (1.f + expf(v));
                } else if (mode == 5) {
                    float sg = 1.f / (1.f + expf(-v));
                    v = (1.f - Pf[idx]) * sg * b2f(Q[idx]);
                } else {
                    float sg = 1.f / (1.f + expf(-v));
                    v = (mode == 2) ? (sg * b2f(P[idx]) + (1.f - sg) * b2f(Q[idx]))
                                    : (b2f(P[idx]) + sg * b2f(Q[idx]));
                }
                vv[cq] = v;
            }
            if (mode >= 4) {
                #pragma unroll
                for (int cq = 0; cq < 4; cq++) outf[idx0[cq]] = vv[cq];
            } else {
                *reinterpret_cast<uint32_t*>(outb + idx0[0]) = pk(vv[0], vv[1]);
                *reinterpret_cast<uint32_t*>(outb + idx0[2]) = pk(vv[2], vv[3]);
            }
        }
    }
}

// ---------------- fused bidirectional chunk-aggregate scan (phase 1) ----------------
__global__ void scan_p1_bi(const float* __restrict__ A, const float* __restrict__ Bv,
                           float* __restrict__ Ach, float* __restrict__ Bchf,
                           float* __restrict__ Bchb) {
    int k = blockIdx.x, b = blockIdx.y, c = threadIdx.x;
    const int clen = Nn / NCH;
    float Pp = 1.f, Bf = 0.f, Bbk = 0.f;
    for (int i = 0; i < clen; i++) {
        int n = k * clen + i;
        size_t idx = ((size_t)(b * Nn + n)) * Cc + c;
        float a = A[idx], bb = Bv[idx];
        Bf = a * Bf + bb;
        Bbk = fmaf(bb, Pp, Bbk);
        Pp *= a;
    }
    Ach[((size_t)(b * NCH + k)) * Cc + c] = Pp;
    Bchf[((size_t)(b * NCH + k)) * Cc + c] = Bf;
    Bchb[((size_t)(b * NCH + (NCH - 1 - k))) * Cc + c] = Bbk;
}

// ---------------- phase 2: inter-chunk prefix for both directions ----------------
__global__ void scan_p2_bi(const float* __restrict__ Ach, const float* __restrict__ Bchf,
                           const float* __restrict__ Bchb, float* __restrict__ Sinf,
                           float* __restrict__ Sinb) {
    int b = blockIdx.x, c = threadIdx.x;
    float sf = 0.f, sb = 0.f;
    for (int k = 0; k < NCH; k++) {
        size_t idx = ((size_t)(b * NCH + k)) * Cc + c;
        Sinf[idx] = sf;
        sf = Ach[idx] * sf + Bchf[idx];
        size_t idxr = ((size_t)(b * NCH + (NCH - 1 - k))) * Cc + c;
        Sinb[idx] = sb;
        sb = Ach[idxr] * sb + Bchb[idx];
    }
}

// ---------------- phase 3: intra-chunk scan + output (R7-validated, two launches) ----------------
__global__ void scan_p3(const float* __restrict__ A, const float* __restrict__ Bv,
                        const bf* __restrict__ O, const bf* __restrict__ u,
                        const float* __restrict__ Sin, bf* __restrict__ y, int dir) {
    int k = blockIdx.x, b = blockIdx.y, c = threadIdx.x;
    const int clen = Nn / NCH;
    float s = Sin[((size_t)(b * NCH + k)) * Cc + c];
    for (int i = 0; i < clen; i++) {
        int tt = k * clen + i;
        int n = dir > 0 ? tt : (Nn - 1 - tt);
        size_t idx = ((size_t)(b * Nn + n)) * Cc + c;
        float a = A[idx];
        s = a * s + Bv[idx];
        float o = b2f(O[idx]);
        y[idx] = __float2bfloat16(o * s + (1.f - o) * b2f(u[idx]));
    }
}

// ---------------- simple forward scan (global branch, bf16 o/u/y) ----------------
__global__ void scan_fwd_simple(const float* __restrict__ A, const float* __restrict__ Bv,
                                const bf* __restrict__ O, const bf* __restrict__ u,
                                bf* __restrict__ y, int Ntok) {
    int b = blockIdx.x, c = threadIdx.x;
    float s = 0.f;
    for (int n = 0; n < Ntok; n++) {
        size_t idx = ((size_t)(b * Ntok + n)) * Cc + c;
        float a = A[idx];
        s = a * s + Bv[idx];
        float o = b2f(O[idx]);
        y[idx] = __float2bfloat16(o * s + (1.f - o) * b2f(u[idx]));
    }
}

// ---------------- bilinear upsample 16->64 (bf16 in/out) ----------------
__global__ void upsample_g(const bf* __restrict__ yg, bf* __restrict__ outp) {
    int n = blockIdx.x, b = blockIdx.y, c = threadIdx.x;
    int h = n >> 6, w = n & 63;
    float sy = h * 0.25f - 0.375f;
    int y0 = (int)floorf(sy); float fy = sy - (float)y0;
    int y1 = y0 + 1; if (y0 < 0) y0 = 0; if (y1 > 15) y1 = 15;
    float sx = w * 0.25f - 0.375f;
    int x0 = (int)floorf(sx); float fx = sx - (float)x0;
    int x1 = x0 + 1; if (x0 < 0) x0 = 0; if (x1 > 15) x1 = 15;
    const bf* base = yg + ((size_t)b * NG) * Cc + c;
    float v00 = b2f(base[(size_t)(y0 * 16 + x0) * Cc]);
    float v01 = b2f(base[(size_t)(y0 * 16 + x1) * Cc]);
    float v10 = b2f(base[(size_t)(y1 * 16 + x0) * Cc]);
    float v11 = b2f(base[(size_t)(y1 * 16 + x1) * Cc]);
    float v = (1.f - fy) * ((1.f - fx) * v00 + fx * v01) + fy * ((1.f - fx) * v10 + fx * v11);
    outp[((size_t)(b * Nn + n)) * Cc + c] = __float2bfloat16(v);
}

// ---------------- 3x3 depthwise conv (bf16 out) ----------------
__global__ void dwconv_k(const float* __restrict__ x, const float* __restrict__ wdw,
                         const float* __restrict__ bdw, bf* __restrict__ vmap) {
    int c = blockIdx.y, b = blockIdx.z;
    int n = blockIdx.x * 256 + threadIdx.x;
    int h = n >> 6, w = n & 63;
    const float* xp = x + ((size_t)(b * Cc + c)) * Nn;
    const float* kp = wdw + c * 9;
    float s = bdw[c];
    #pragma unroll
    for (int kh = 0; kh < 3; kh++) {
        int hh = h + kh - 1;
        if (hh < 0 || hh > 63) continue;
        #pragma unroll
        for (int kw = 0; kw < 3; kw++) {
            int ww2 = w + kw - 1;
            if (ww2 < 0 || ww2 > 63) continue;
            s += xp[hh * 64 + ww2] * kp[kh * 3 + kw];
        }
    }
    vmap[((size_t)(b * Cc + c)) * Nn + n] = __float2bfloat16(s);
}

// ---------------- host ----------------
static inline void gemm(const bf* A0, const bf* A1, const bf* A2, int bcast, int nseg,
                        int tshift, const float* Wm, const float* bias, const float* aux,
                        int tmask, const bf* P, const float* Pf, const bf* Q,
                        void* outp, int M, int mode) {
    gemm_k<<<dim3(M / 128, 2), 256>>>(A0, A1, A2, bcast, nseg, tshift, Wm, bias, aux, tmask,
                                      P, Pf, Q, outp, mode);
}

#define SYMF(p, s) float* p; cudaGetSymbolAddress((void**)&p, s)
#define SYMB(p, s) bf* p;    cudaGetSymbolAddress((void**)&p, s)

extern "C" void kernel_launch(void* const* d_in, const int* in_sizes, int n_in,
                              void* d_out, int out_size) {
    const float* x    = (const float*)d_in[0];
    const float* Wt   = (const float*)d_in[1];
    const float* bt   = (const float*)d_in[2];
    const float* pf   = (const float*)d_in[3];
    const float* pg   = (const float*)d_in[4];
    const float* lng  = (const float*)d_in[5];
    const float* lnb  = (const float*)d_in[6];
    const float* Wf   = (const float*)d_in[7];
    const float* bfb  = (const float*)d_in[8];
    const float* Wwm  = (const float*)d_in[9];
    const float* bw   = (const float*)d_in[10];
    const float* Wo   = (const float*)d_in[11];
    const float* bo   = (const float*)d_in[12];
    const float* Wr   = (const float*)d_in[13];
    const float* br   = (const float*)d_in[14];
    const float* Wgi  = (const float*)d_in[15];
    const float* bgi  = (const float*)d_in[16];
    const float* dww  = (const float*)d_in[17];
    const float* dwb  = (const float*)d_in[18];
    const float* Wl   = (const float*)d_in[19];
    const float* bl   = (const float*)d_in[20];
    const float* Wlf  = (const float*)d_in[21];
    const float* blf  = (const float*)d_in[22];
    const float* Wout = (const float*)d_in[23];
    const float* bout = (const float*)d_in[24];
    float* outp = (float*)d_out;

    SYMB(xs, g_xs);   SYMB(u, g_u);     SYMF(a_, g_a);    SYMF(b_, g_b);    SYMB(o_, g_o);
    SYMB(yf, g_yf);   SYMB(yb, g_yb);   SYMB(y, g_y);     SYMB(ygs, g_ygs); SYMB(z, g_z);
    SYMB(vmap, g_vmap); SYMB(vt, g_vt); SYMB(v, g_v);     SYMB(tmp, g_tmp); SYMB(uo, g_uo);
    SYMF(posf, g_posf); SYMF(posg, g_posg); SYMF(mpart, g_mpart);
    SYMB(cctx, g_cctx); SYMB(cctx2, g_cctx2);
    SYMF(Ach, g_Ach); SYMF(Bchf, g_Bchf); SYMF(Bchb, g_Bchb);
    SYMF(Sinf, g_Sinf); SYMF(Sinb, g_Sinb);
    SYMF(xgt, g_xgt); SYMB(xgs, g_xgs); SYMB(ug, g_ug);
    SYMF(a2, g_a2);   SYMF(b2, g_b2);   SYMB(o2, g_o2);   SYMB(yg, g_yg);

    dim3 tb(32, 8);

    // ---- fine branch ----
    trans_cn_nc<<<dim3(128, 8, Bb), tb>>>(x, xs, Nn);
    pos_up_k<<<Nn, Cc>>>(pf, posf);
    gemm(xs, 0, 0, 0, 1, 12, Wt, bt, posf, 4095, 0, 0, 0, u, Bb * Nn, 0);

    mean_part8<<<dim3(32, Bb), 256>>>(u, mpart, Nn, 32);
    ln_ctx_k<<<Bb, Cc>>>(mpart, 256, 1.f / Nn, lng, lnb, cctx);

    // gates fused into GEMM epilogues (a f32 -> o bf16 -> b f32 reads a)
    gemm(u, cctx, 0, 2, 2, 12, Wf, bfb, 0, 0, 0, 0, 0, a_, Bb * Nn, 4);
    gemm(u, cctx, 0, 2, 2, 12, Wo, bo, 0, 0, 0, 0, 0, o_, Bb * Nn, 1);
    gemm(u, cctx, 0, 2, 2, 12, Wwm, bw, 0, 0, 0, a_, u, b_, Bb * Nn, 5);

    scan_p1_bi<<<dim3(NCH, Bb), Cc>>>(a_, b_, Ach, Bchf, Bchb);
    scan_p2_bi<<<Bb, Cc>>>(Ach, Bchf, Bchb, Sinf, Sinb);
    scan_p3<<<dim3(NCH, Bb), Cc>>>(a_, b_, o_, u, Sinf, yf, 1);
    scan_p3<<<dim3(NCH, Bb), Cc>>>(a_, b_, o_, u, Sinb, yb, -1);

    // rho GEMM + blend fused
    gemm(u, yf, yb, 0, 3, 12, Wr, br, 0, 0, yf, 0, yb, y, Bb * Nn, 2);

    // ---- global branch ----
    avgpool_k<<<dim3(Cc, Bb), 256>>>(x, xgt);
    trans_cn_nc<<<dim3(8, 8, Bb), tb>>>(xgt, xgs, NG);
    pos_down_k<<<NG, Cc>>>(pg, posg);
    gemm(xgs, 0, 0, 0, 1, 8, Wt, bt, posg, 255, 0, 0, 0, ug, Bb * NG, 0);

    mean_part8<<<dim3(8, Bb), 256>>>(ug, mpart, NG, 8);
    ln_ctx_k<<<Bb, Cc>>>(mpart, 64, 1.f / NG, lng, lnb, cctx2);

    gemm(ug, cctx2, 0, 2, 2, 8, Wf, bfb, 0, 0, 0, 0, 0, a2, Bb * NG, 4);
    gemm(ug, cctx2, 0, 2, 2, 8, Wo, bo, 0, 0, 0, 0, 0, o2, Bb * NG, 1);
    gemm(ug, cctx2, 0, 2, 2, 8, Wwm, bw, 0, 0, 0, a2, ug, b2, Bb * NG, 5);
    scan_fwd_simple<<<Bb, Cc>>>(a2, b2, o2, ug, yg, NG);
    upsample_g<<<dim3(Nn, Bb), Cc>>>(yg, ygs);

    // lam GEMM + blend fused: z = y + sig(..)*ygs
    gemm(y, ygs, u, 0, 3, 12, Wgi, bgi, 0, 0, y, 0, ygs, z, Bb * Nn, 3);

    // ---- local depthwise branch ----
    dwconv_k<<<dim3(16, Cc, Bb), 256>>>(x, dww, dwb, vmap);
    trans_cn_nc_bf<<<dim3(128, 8, Bb), tb>>>(vmap, vt, Nn);
    gemm(vt, 0, 0, 0, 1, 12, Wl, bl, 0, 0, 0, 0, 0, v, Bb * Nn, 0);
    // eta GEMM + blend fused
    gemm(v, z, 0, 0, 2, 12, Wlf, blf, 0, 0, v, 0, z, uo, Bb * Nn, 2);

    // ---- output proj + residual ----
    gemm(uo, 0, 0, 0, 1, 12, Wout, bout, 0, 0, 0, 0, 0, tmp, Bb * Nn, 0);
    trans_add_k<<<dim3(128, 8, Bb), tb>>>(tmp, x, outp);
}

// round 10
// speedup vs baseline: 1.4158x; 1.1990x over previous
#include <cuda_runtime.h>
#include <cuda_bf16.h>
#include <stdint.h>
#include <math.h>

typedef __nv_bfloat16 bf;

#define Bb 8
#define Cc 256
#define Nn 4096
#define NG 256
#define NCH 64
#define BNC (Bb*Nn*Cc)
#define BGC (Bb*NG*Cc)

// ---------------- scratch (static __device__ — no allocation) ----------------
__device__ bf    g_xs[BNC];
__device__ bf    g_u[BNC];
__device__ float g_a[BNC];
__device__ bf    g_sg[BNC];
__device__ bf    g_o[BNC];
__device__ bf    g_yf[BNC];
__device__ bf    g_yb[BNC];
__device__ bf    g_y[BNC];
__device__ bf    g_ygs[BNC];
__device__ bf    g_z[BNC];
__device__ bf    g_vmap[BNC];
__device__ bf    g_vt[BNC];
__device__ bf    g_v[BNC];
__device__ bf    g_tmp[BNC];
__device__ bf    g_uo[BNC];
__device__ float g_posf[Nn*Cc];
__device__ float g_posg[NG*Cc];
__device__ float g_mpart[Bb*256*Cc];
__device__ bf    g_cctx[Bb*Cc];
__device__ bf    g_cctx2[Bb*Cc];
__device__ float g_cbF[3*Bb*Cc];
__device__ float g_cbG[3*Bb*Cc];
__device__ float g_Ach[Bb*NCH*Cc];
__device__ float g_Bchf[Bb*NCH*Cc];
__device__ float g_Bchb[Bb*NCH*Cc];
__device__ float g_Sinf[Bb*NCH*Cc];
__device__ float g_Sinb[Bb*NCH*Cc];
__device__ float g_xgt[BGC];
__device__ bf    g_xgs[BGC];
__device__ bf    g_ug[BGC];
__device__ float g_a2[BGC];
__device__ bf    g_sg2[BGC];
__device__ bf    g_o2[BGC];
__device__ bf    g_yg[BGC];

__device__ __forceinline__ float b2f(bf x) { return __bfloat162float(x); }

// ---------------- transpose [B,C,Ntok] f32 -> [B,Ntok,C] bf16 ----------------
__global__ void trans_cn_nc(const float* __restrict__ in, bf* __restrict__ outp, int Ntok) {
    __shared__ float tile[32][33];
    int b = blockIdx.z;
    int n0 = blockIdx.x * 32, c0 = blockIdx.y * 32;
    int tx = threadIdx.x, ty = threadIdx.y;
    for (int i = ty; i < 32; i += 8)
        tile[i][tx] = in[((size_t)(b * Cc + c0 + i)) * Ntok + n0 + tx];
    __syncthreads();
    for (int i = ty; i < 32; i += 8)
        outp[((size_t)(b * Ntok + n0 + i)) * Cc + c0 + tx] = __float2bfloat16(tile[tx][i]);
}

// ---------------- transpose [B,C,Ntok] bf16 -> [B,Ntok,C] bf16 ----------------
__global__ void trans_cn_nc_bf(const bf* __restrict__ in, bf* __restrict__ outp, int Ntok) {
    __shared__ bf tile[32][33];
    int b = blockIdx.z;
    int n0 = blockIdx.x * 32, c0 = blockIdx.y * 32;
    int tx = threadIdx.x, ty = threadIdx.y;
    for (int i = ty; i < 32; i += 8)
        tile[i][tx] = in[((size_t)(b * Cc + c0 + i)) * Ntok + n0 + tx];
    __syncthreads();
    for (int i = ty; i < 32; i += 8)
        outp[((size_t)(b * Ntok + n0 + i)) * Cc + c0 + tx] = tile[tx][i];
}

// ---------------- transpose-add: out[b,c,n] = x[b,c,n] + proj_bf16[b,n,c] ----------------
__global__ void trans_add_k(const bf* __restrict__ proj, const float* __restrict__ x,
                            float* __restrict__ outp) {
    __shared__ float tile[32][33];
    int b = blockIdx.z;
    int n0 = blockIdx.x * 32, c0 = blockIdx.y * 32;
    int tx = threadIdx.x, ty = threadIdx.y;
    for (int i = ty; i < 32; i += 8)
        tile[i][tx] = b2f(proj[((size_t)(b * Nn + n0 + i)) * Cc + c0 + tx]);
    __syncthreads();
    for (int i = ty; i < 32; i += 8) {
        size_t idx = ((size_t)(b * Cc + c0 + i)) * Nn + n0 + tx;
        outp[idx] = x[idx] + tile[tx][i];
    }
}

// ---------------- pos embed upsample 32->64 ----------------
__global__ void pos_up_k(const float* __restrict__ pos, float* __restrict__ outp) {
    int n = blockIdx.x, c = threadIdx.x;
    int h = n >> 6, w = n & 63;
    float sy = h * 0.5f - 0.25f;
    int y0 = (int)floorf(sy); float fy = sy - (float)y0;
    int y1 = y0 + 1; if (y0 < 0) y0 = 0; if (y1 > 31) y1 = 31;
    float sx = w * 0.5f - 0.25f;
    int x0 = (int)floorf(sx); float fx = sx - (float)x0;
    int x1 = x0 + 1; if (x0 < 0) x0 = 0; if (x1 > 31) x1 = 31;
    const float* p = pos + (size_t)c * 1024;
    float v = (1.f - fy) * ((1.f - fx) * p[y0 * 32 + x0] + fx * p[y0 * 32 + x1])
            + fy * ((1.f - fx) * p[y1 * 32 + x0] + fx * p[y1 * 32 + x1]);
    outp[(size_t)n * Cc + c] = v;
}

// ---------------- pos embed antialiased downsample 32->16 ----------------
__global__ void pos_down_k(const float* __restrict__ pos, float* __restrict__ outp) {
    int g = blockIdx.x, c = threadIdx.x;
    int gh = g >> 4, gw = g & 15;
    float wy[4], wx[4];
    int iy[4], ix[4];
    float sy = 2.f * gh + 0.5f, sx = 2.f * gw + 0.5f;
    float wsy = 0.f, wsx = 0.f;
    for (int tp = 0; tp < 4; tp++) {
        int i = 2 * gh - 1 + tp;
        float wg = 0.f;
        if (i >= 0 && i < 32) wg = fmaxf(0.f, 1.f - fabsf((float)i - sy) * 0.5f);
        iy[tp] = i < 0 ? 0 : (i > 31 ? 31 : i); wy[tp] = wg; wsy += wg;
        int j = 2 * gw - 1 + tp;
        float wg2 = 0.f;
        if (j >= 0 && j < 32) wg2 = fmaxf(0.f, 1.f - fabsf((float)j - sx) * 0.5f);
        ix[tp] = j < 0 ? 0 : (j > 31 ? 31 : j); wx[tp] = wg2; wsx += wg2;
    }
    const float* p = pos + (size_t)c * 1024;
    float acc = 0.f;
    for (int a = 0; a < 4; a++)
        for (int bq = 0; bq < 4; bq++)
            acc += wy[a] * wx[bq] * p[iy[a] * 32 + ix[bq]];
    outp[(size_t)g * Cc + c] = acc / (wsy * wsx);
}

// ---------------- 4x4 avg pool ----------------
__global__ void avgpool_k(const float* __restrict__ x, float* __restrict__ xgt) {
    int c = blockIdx.x, b = blockIdx.y, g = threadIdx.x;
    int gh = g >> 4, gw = g & 15;
    const float* xp = x + ((size_t)(b * Cc + c)) * Nn;
    float s = 0.f;
    #pragma unroll
    for (int dh = 0; dh < 4; dh++)
        #pragma unroll
        for (int dw = 0; dw < 4; dw++)
            s += xp[(gh * 4 + dh) * 64 + gw * 4 + dw];
    xgt[((size_t)(b * Cc + c)) * NG + g] = s * (1.f / 16.f);
}

// ---------------- partial mean over tokens, vectorized ----------------
__global__ void mean_part8(const bf* __restrict__ u, float* __restrict__ part,
                           int Ntok, int P) {
    int p = blockIdx.x, b = blockIdx.y;
    int t = threadIdx.x;
    int c0 = (t & 31) * 8;
    int tg = t >> 5;
    int per = Ntok / P / 8;
    float s[8];
    #pragma unroll
    for (int j = 0; j < 8; j++) s[j] = 0.f;
    int nbase = p * (Ntok / P) + tg * per;
    for (int i = 0; i < per; i++) {
        int n = nbase + i;
        uint4 q = *reinterpret_cast<const uint4*>(u + ((size_t)(b * Ntok + n)) * Cc + c0);
        const bf* e = reinterpret_cast<const bf*>(&q);
        #pragma unroll
        for (int j = 0; j < 8; j++) s[j] += b2f(e[j]);
    }
    float* dst = part + ((size_t)(b * P * 8 + p * 8 + tg)) * Cc + c0;
    *reinterpret_cast<float4*>(dst)     = make_float4(s[0], s[1], s[2], s[3]);
    *reinterpret_cast<float4*>(dst + 4) = make_float4(s[4], s[5], s[6], s[7]);
}

// ---------------- layernorm of pooled context -> bf16 ----------------
__global__ void ln_ctx_k(const float* __restrict__ part, int P, float invN,
                         const float* __restrict__ gam, const float* __restrict__ bet,
                         bf* __restrict__ outp) {
    int b = blockIdx.x, c = threadIdx.x;
    float s = 0.f;
    for (int p = 0; p < P; p++) s += part[((size_t)(b * P + p)) * Cc + c];
    float m = s * invN;
    __shared__ float red[Cc];
    __shared__ float s_mu, s_var;
    red[c] = m; __syncthreads();
    for (int off = 128; off; off >>= 1) { if (c < off) red[c] += red[c + off]; __syncthreads(); }
    if (c == 0) s_mu = red[0] * (1.f / Cc);
    __syncthreads();
    float dm = m - s_mu;
    red[c] = dm * dm; __syncthreads();
    for (int off = 128; off; off >>= 1) { if (c < off) red[c] += red[c + off]; __syncthreads(); }
    if (c == 0) s_var = red[0] * (1.f / Cc);
    __syncthreads();
    outp[b * Cc + c] = __float2bfloat16(dm * rsqrtf(s_var + 1e-5f) * gam[c] + bet[c]);
}

// ---------------- ctx projection: cb[gate][r][n] = c[r] @ W_c(gate) + bias(gate) ----------------
// grid (3, 8), block 256. W rows 256..511 are the context half of [u|c] weights.
__global__ void ctx_proj_k(const bf* __restrict__ c,
                           const float* __restrict__ W0, const float* __restrict__ W1,
                           const float* __restrict__ W2,
                           const float* __restrict__ b0, const float* __restrict__ b1,
                           const float* __restrict__ b2,
                           float* __restrict__ cb) {
    int gate = blockIdx.x, r = blockIdx.y, n = threadIdx.x;
    const float* W = gate == 0 ? W0 : (gate == 1 ? W1 : W2);
    const float* bias = gate == 0 ? b0 : (gate == 1 ? b1 : b2);
    __shared__ float cs[Cc];
    cs[n] = b2f(c[r * Cc + n]);
    __syncthreads();
    float s = bias[n];
    for (int k = 0; k < Cc; k++)
        s = fmaf(cs[k], W[(size_t)(256 + k) * Cc + n], s);
    cb[((gate * Bb + r) << 8) + n] = s;
}

// ---------------- bf16 tensor-core segmented GEMM ----------------
// grid (M/128, nb). modes:
// 0: out(bf16) = acc+bias (+aux fp32, row m&tmask)
// 2: t=sig(acc+bias); out(bf16) = t*P + (1-t)*Q
// 3: t=sig(acc+bias); out(bf16) = P + t*Q
// 6: fused gates (nb=6, gate=blockIdx.y>>1): v = acc + cb[gate][m>>tshift][n];
//    gate0 -> outp f32 = sigmoid(-v); gate1 -> P bf16 = sigmoid(v); gate2 -> Q bf16 = sigmoid(v)
//    (A1/A2 carry W1/W2 pointers; aux carries cb)
__device__ __forceinline__ uint32_t pk(float lo, float hi) {
    uint32_t r;
    asm("cvt.rn.bf16x2.f32 %0, %1, %2;" : "=r"(r) : "f"(hi), "f"(lo));
    return r;
}

__device__ __forceinline__ void g2r(
    const bf* __restrict__ A0, const bf* __restrict__ A1, const bf* __restrict__ A2,
    int bcast, int tshift, const float* __restrict__ Wm,
    int tile, int m0, int n0, int am, int ah, int wkp, int wnq,
    uint32_t ra[8], uint32_t rw[8], int mode) {
    int k0 = tile * 32;
    int seg = k0 >> 8;
    const bf* p = (mode == 6) ? A0 : ((seg == 0) ? A0 : ((seg == 1) ? A1 : A2));
    bool bc = (mode != 6) && ((bcast >> seg) & 1);
    int row = bc ? ((m0 + am) >> tshift) : (m0 + am);
    const bf* ap = p + ((size_t)row << 8) + (k0 & 255) + ah;
    uint4 q0 = *reinterpret_cast<const uint4*>(ap);
    uint4 q1 = *reinterpret_cast<const uint4*>(ap + 8);
    ra[0] = q0.x; ra[1] = q0.y; ra[2] = q0.z; ra[3] = q0.w;
    ra[4] = q1.x; ra[5] = q1.y; ra[6] = q1.z; ra[7] = q1.w;
    const float* wp = Wm + ((size_t)(k0 + 2 * wkp) << 8) + n0 + wnq;
    float4 w0 = *reinterpret_cast<const float4*>(wp);
    float4 w1 = *reinterpret_cast<const float4*>(wp + 4);
    float4 w2 = *reinterpret_cast<const float4*>(wp + 256);
    float4 w3 = *reinterpret_cast<const float4*>(wp + 260);
    rw[0] = pk(w0.x, w2.x); rw[1] = pk(w0.y, w2.y);
    rw[2] = pk(w0.z, w2.z); rw[3] = pk(w0.w, w2.w);
    rw[4] = pk(w1.x, w3.x); rw[5] = pk(w1.y, w3.y);
    rw[6] = pk(w1.z, w3.z); rw[7] = pk(w1.w, w3.w);
}

__global__ __launch_bounds__(256) void gemm_k(
    const bf* __restrict__ A0, const bf* __restrict__ A1, const bf* __restrict__ A2,
    int bcast, int nseg, int tshift,
    const float* __restrict__ Wm, const float* __restrict__ bias,
    const float* __restrict__ aux, int tmask,
    const bf* __restrict__ P, const float* __restrict__ Pf, const bf* __restrict__ Q,
    void* __restrict__ outp, int mode) {
    __shared__ uint32_t As[2][128][20];
    __shared__ uint32_t Ws[2][16][136];
    const int t = threadIdx.x;
    const int m0 = blockIdx.x * 128;
    const int gate = (mode == 6) ? (blockIdx.y >> 1) : 0;
    const int n0 = (mode == 6) ? ((blockIdx.y & 1) * 128) : (blockIdx.y * 128);
    const float* Wsel = Wm;
    if (mode == 6) {
        if (gate == 1) Wsel = (const float*)A1;
        else if (gate == 2) Wsel = (const float*)A2;
    }
    const int wid = t >> 5, lane = t & 31;
    const int wm = (wid >> 2) * 64;
    const int wn = (wid & 3) * 32;
    const int g = lane >> 2, tig = lane & 3;
    const int am = t >> 1;
    const int ah = (t & 1) * 16;
    const int wkp = t >> 4;
    const int wnq = (t & 15) * 8;

    float acc[4][4][4];
    #pragma unroll
    for (int mt = 0; mt < 4; mt++)
        #pragma unroll
        for (int nt = 0; nt < 4; nt++)
            #pragma unroll
            for (int cq = 0; cq < 4; cq++) acc[mt][nt][cq] = 0.f;

    const int T = nseg << 3;
    uint32_t ra[8], rw[8];

    g2r(A0, A1, A2, bcast, tshift, Wsel, 0, m0, n0, am, ah, wkp, wnq, ra, rw, mode);
    {
        int kp0 = ah >> 1;
        *reinterpret_cast<uint4*>(&As[0][am][kp0])     = make_uint4(ra[0], ra[1], ra[2], ra[3]);
        *reinterpret_cast<uint4*>(&As[0][am][kp0 + 4]) = make_uint4(ra[4], ra[5], ra[6], ra[7]);
        *reinterpret_cast<uint4*>(&Ws[0][wkp][wnq])     = make_uint4(rw[0], rw[1], rw[2], rw[3]);
        *reinterpret_cast<uint4*>(&Ws[0][wkp][wnq + 4]) = make_uint4(rw[4], rw[5], rw[6], rw[7]);
    }
    __syncthreads();

    for (int tt = 0; tt < T; tt++) {
        if (tt + 1 < T)
            g2r(A0, A1, A2, bcast, tshift, Wsel, tt + 1, m0, n0, am, ah, wkp, wnq, ra, rw, mode);
        const int buf = tt & 1;
        #pragma unroll
        for (int kp = 0; kp < 16; kp += 8) {
            uint32_t af[4][4], bfr[4][2];
            #pragma unroll
            for (int mt = 0; mt < 4; mt++) {
                int r = wm + mt * 16 + g;
                af[mt][0] = As[buf][r][kp + tig];
                af[mt][1] = As[buf][r + 8][kp + tig];
                af[mt][2] = As[buf][r][kp + tig + 4];
                af[mt][3] = As[buf][r + 8][kp + tig + 4];
            }
            #pragma unroll
            for (int nt = 0; nt < 4; nt++) {
                bfr[nt][0] = Ws[buf][kp + tig][wn + nt * 8 + g];
                bfr[nt][1] = Ws[buf][kp + tig + 4][wn + nt * 8 + g];
            }
            #pragma unroll
            for (int mt = 0; mt < 4; mt++)
                #pragma unroll
                for (int nt = 0; nt < 4; nt++) {
                    asm volatile(
                        "mma.sync.aligned.m16n8k16.row.col.f32.bf16.bf16.f32 "
                        "{%0,%1,%2,%3}, {%4,%5,%6,%7}, {%8,%9}, {%0,%1,%2,%3};"
                        : "+f"(acc[mt][nt][0]), "+f"(acc[mt][nt][1]),
                          "+f"(acc[mt][nt][2]), "+f"(acc[mt][nt][3])
                        : "r"(af[mt][0]), "r"(af[mt][1]), "r"(af[mt][2]), "r"(af[mt][3]),
                          "r"(bfr[nt][0]), "r"(bfr[nt][1]));
                }
        }
        if (tt + 1 < T) {
            const int nb = (tt + 1) & 1;
            int kp0 = ah >> 1;
            *reinterpret_cast<uint4*>(&As[nb][am][kp0])     = make_uint4(ra[0], ra[1], ra[2], ra[3]);
            *reinterpret_cast<uint4*>(&As[nb][am][kp0 + 4]) = make_uint4(ra[4], ra[5], ra[6], ra[7]);
            *reinterpret_cast<uint4*>(&Ws[nb][wkp][wnq])     = make_uint4(rw[0], rw[1], rw[2], rw[3]);
            *reinterpret_cast<uint4*>(&Ws[nb][wkp][wnq + 4]) = make_uint4(rw[4], rw[5], rw[6], rw[7]);
            __syncthreads();
        }
    }

    bf* outb = (bf*)outp;
    float* outf = (float*)outp;
    bf* sgout = (bf*)P;
    bf* oout = (bf*)Q;
    #pragma unroll
    for (int mt = 0; mt < 4; mt++) {
        #pragma unroll
        for (int nt = 0; nt < 4; nt++) {
            int r = m0 + wm + mt * 16 + g;
            int cN = n0 + wn + nt * 8 + 2 * tig;
            float vv[4];
            size_t idx0[4];
            #pragma unroll
            for (int cq = 0; cq < 4; cq++) {
                int m = r + (cq >> 1) * 8;
                int n = cN + (cq & 1);
                size_t idx = ((size_t)m << 8) + n;
                idx0[cq] = idx;
                float v = acc[mt][nt][cq];
                if (mode == 6) {
                    v += aux[((size_t)((gate << 3) + (m >> tshift)) << 8) + n];
                    vv[cq] = (gate == 0) ? 1.f / (1.f + expf(v))
                                         : 1.f / (1.f + expf(-v));
                } else {
                    v += bias[n];
                    if (mode == 0) {
                        if (aux) v += aux[((size_t)(m & tmask) << 8) + n];
                    } else {
                        float sg = 1.f / (1.f + expf(-v));
                        v = (mode == 2) ? (sg * b2f(P[idx]) + (1.f - sg) * b2f(Q[idx]))
                                        : (b2f(P[idx]) + sg * b2f(Q[idx]));
                    }
                    vv[cq] = v;
                }
            }
            if (mode == 6) {
                if (gate == 0) {
                    #pragma unroll
                    for (int cq = 0; cq < 4; cq++) outf[idx0[cq]] = vv[cq];
                } else {
                    bf* dst = (gate == 1) ? sgout : oout;
                    *reinterpret_cast<uint32_t*>(dst + idx0[0]) = pk(vv[0], vv[1]);
                    *reinterpret_cast<uint32_t*>(dst + idx0[2]) = pk(vv[2], vv[3]);
                }
            } else {
                *reinterpret_cast<uint32_t*>(outb + idx0[0]) = pk(vv[0], vv[1]);
                *reinterpret_cast<uint32_t*>(outb + idx0[2]) = pk(vv[2], vv[3]);
            }
        }
    }
}

// ---------------- fused bidirectional chunk-aggregate scan (phase 1) ----------------
// b computed inline: b = (1-a) * sg * u
__global__ void scan_p1_bi(const float* __restrict__ A, const bf* __restrict__ SG,
                           const bf* __restrict__ U,
                           float* __restrict__ Ach, float* __restrict__ Bchf,
                           float* __restrict__ Bchb) {
    int k = blockIdx.x, b = blockIdx.y, c = threadIdx.x;
    const int clen = Nn / NCH;
    float Pp = 1.f, Bf = 0.f, Bbk = 0.f;
    for (int i = 0; i < clen; i++) {
        int n = k * clen + i;
        size_t idx = ((size_t)(b * Nn + n)) * Cc + c;
        float a = A[idx];
        float bb = (1.f - a) * b2f(SG[idx]) * b2f(U[idx]);
        Bf = a * Bf + bb;
        Bbk = fmaf(bb, Pp, Bbk);
        Pp *= a;
    }
    Ach[((size_t)(b * NCH + k)) * Cc + c] = Pp;
    Bchf[((size_t)(b * NCH + k)) * Cc + c] = Bf;
    Bchb[((size_t)(b * NCH + (NCH - 1 - k))) * Cc + c] = Bbk;
}

// ---------------- phase 2: inter-chunk prefix for both directions ----------------
__global__ void scan_p2_bi(const float* __restrict__ Ach, const float* __restrict__ Bchf,
                           const float* __restrict__ Bchb, float* __restrict__ Sinf,
                           float* __restrict__ Sinb) {
    int b = blockIdx.x, c = threadIdx.x;
    float sf = 0.f, sb = 0.f;
    for (int k = 0; k < NCH; k++) {
        size_t idx = ((size_t)(b * NCH + k)) * Cc + c;
        Sinf[idx] = sf;
        sf = Ach[idx] * sf + Bchf[idx];
        size_t idxr = ((size_t)(b * NCH + (NCH - 1 - k))) * Cc + c;
        Sinb[idx] = sb;
        sb = Ach[idxr] * sb + Bchb[idx];
    }
}

// ---------------- phase 3: intra-chunk scan + output ----------------
__global__ void scan_p3(const float* __restrict__ A, const bf* __restrict__ SG,
                        const bf* __restrict__ O, const bf* __restrict__ u,
                        const float* __restrict__ Sin, bf* __restrict__ y, int dir) {
    int k = blockIdx.x, b = blockIdx.y, c = threadIdx.x;
    const int clen = Nn / NCH;
    float s = Sin[((size_t)(b * NCH + k)) * Cc + c];
    for (int i = 0; i < clen; i++) {
        int tt = k * clen + i;
        int n = dir > 0 ? tt : (Nn - 1 - tt);
        size_t idx = ((size_t)(b * Nn + n)) * Cc + c;
        float a = A[idx];
        float uf = b2f(u[idx]);
        float bb = (1.f - a) * b2f(SG[idx]) * uf;
        s = a * s + bb;
        float o = b2f(O[idx]);
        y[idx] = __float2bfloat16(o * s + (1.f - o) * uf);
    }
}

// ---------------- simple forward scan (global branch) ----------------
__global__ void scan_fwd_simple(const float* __restrict__ A, const bf* __restrict__ SG,
                                const bf* __restrict__ O, const bf* __restrict__ u,
                                bf* __restrict__ y, int Ntok) {
    int b = blockIdx.x, c = threadIdx.x;
    float s = 0.f;
    for (int n = 0; n < Ntok; n++) {
        size_t idx = ((size_t)(b * Ntok + n)) * Cc + c;
        float a = A[idx];
        float uf = b2f(u[idx]);
        float bb = (1.f - a) * b2f(SG[idx]) * uf;
        s = a * s + bb;
        float o = b2f(O[idx]);
        y[idx] = __float2bfloat16(o * s + (1.f - o) * uf);
    }
}

// ---------------- bilinear upsample 16->64 (bf16 in/out) ----------------
__global__ void upsample_g(const bf* __restrict__ yg, bf* __restrict__ outp) {
    int n = blockIdx.x, b = blockIdx.y, c = threadIdx.x;
    int h = n >> 6, w = n & 63;
    float sy = h * 0.25f - 0.375f;
    int y0 = (int)floorf(sy); float fy = sy - (float)y0;
    int y1 = y0 + 1; if (y0 < 0) y0 = 0; if (y1 > 15) y1 = 15;
    float sx = w * 0.25f - 0.375f;
    int x0 = (int)floorf(sx); float fx = sx - (float)x0;
    int x1 = x0 + 1; if (x0 < 0) x0 = 0; if (x1 > 15) x1 = 15;
    const bf* base = yg + ((size_t)b * NG) * Cc + c;
    float v00 = b2f(base[(size_t)(y0 * 16 + x0) * Cc]);
    float v01 = b2f(base[(size_t)(y0 * 16 + x1) * Cc]);
    float v10 = b2f(base[(size_t)(y1 * 16 + x0) * Cc]);
    float v11 = b2f(base[(size_t)(y1 * 16 + x1) * Cc]);
    float v = (1.f - fy) * ((1.f - fx) * v00 + fx * v01) + fy * ((1.f - fx) * v10 + fx * v11);
    outp[((size_t)(b * Nn + n)) * Cc + c] = __float2bfloat16(v);
}

// ---------------- 3x3 depthwise conv (bf16 out) ----------------
__global__ void dwconv_k(const float* __restrict__ x, const float* __restrict__ wdw,
                         const float* __restrict__ bdw, bf* __restrict__ vmap) {
    int c = blockIdx.y, b = blockIdx.z;
    int n = blockIdx.x * 256 + threadIdx.x;
    int h = n >> 6, w = n & 63;
    const float* xp = x + ((size_t)(b * Cc + c)) * Nn;
    const float* kp = wdw + c * 9;
    float s = bdw[c];
    #pragma unroll
    for (int kh = 0; kh < 3; kh++) {
        int hh = h + kh - 1;
        if (hh < 0 || hh > 63) continue;
        #pragma unroll
        for (int kw = 0; kw < 3; kw++) {
            int ww2 = w + kw - 1;
            if (ww2 < 0 || ww2 > 63) continue;
            s += xp[hh * 64 + ww2] * kp[kh * 3 + kw];
        }
    }
    vmap[((size_t)(b * Cc + c)) * Nn + n] = __float2bfloat16(s);
}

// ---------------- host ----------------
static inline void gemm(const bf* A0, const bf* A1, const bf* A2, int bcast, int nseg,
                        int tshift, const float* Wm, const float* bias, const float* aux,
                        int tmask, const bf* P, const float* Pf, const bf* Q,
                        void* outp, int M, int mode) {
    gemm_k<<<dim3(M / 128, 2), 256>>>(A0, A1, A2, bcast, nseg, tshift, Wm, bias, aux, tmask,
                                      P, Pf, Q, outp, mode);
}

// fused 3-gate GEMM: K=256 (u only), gate outputs a(f32)/sg(bf16)/o(bf16), ctx via cb
static inline void gemm_gates(const bf* A, const float* W0, const float* W1, const float* W2,
                              const float* cb, int tshift,
                              float* a_out, bf* sg_out, bf* o_out, int M) {
    gemm_k<<<dim3(M / 128, 6), 256>>>(A, (const bf*)W1, (const bf*)W2, 0, 1, tshift,
                                      W0, W0, cb, 0, sg_out, 0, o_out, a_out, 6);
}

#define SYMF(p, s) float* p; cudaGetSymbolAddress((void**)&p, s)
#define SYMB(p, s) bf* p;    cudaGetSymbolAddress((void**)&p, s)

extern "C" void kernel_launch(void* const* d_in, const int* in_sizes, int n_in,
                              void* d_out, int out_size) {
    const float* x    = (const float*)d_in[0];
    const float* Wt   = (const float*)d_in[1];
    const float* bt   = (const float*)d_in[2];
    const float* pf   = (const float*)d_in[3];
    const float* pg   = (const float*)d_in[4];
    const float* lng  = (const float*)d_in[5];
    const float* lnb  = (const float*)d_in[6];
    const float* Wf   = (const float*)d_in[7];
    const float* bfb  = (const float*)d_in[8];
    const float* Wwm  = (const float*)d_in[9];
    const float* bw   = (const float*)d_in[10];
    const float* Wo   = (const float*)d_in[11];
    const float* bo   = (const float*)d_in[12];
    const float* Wr   = (const float*)d_in[13];
    const float* br   = (const float*)d_in[14];
    const float* Wgi  = (const float*)d_in[15];
    const float* bgi  = (const float*)d_in[16];
    const float* dww  = (const float*)d_in[17];
    const float* dwb  = (const float*)d_in[18];
    const float* Wl   = (const float*)d_in[19];
    const float* bl   = (const float*)d_in[20];
    const float* Wlf  = (const float*)d_in[21];
    const float* blf  = (const float*)d_in[22];
    const float* Wout = (const float*)d_in[23];
    const float* bout = (const float*)d_in[24];
    float* outp = (float*)d_out;

    SYMB(xs, g_xs);   SYMB(u, g_u);     SYMF(a_, g_a);    SYMB(sg, g_sg);   SYMB(o_, g_o);
    SYMB(yf, g_yf);   SYMB(yb, g_yb);   SYMB(y, g_y);     SYMB(ygs, g_ygs); SYMB(z, g_z);
    SYMB(vmap, g_vmap); SYMB(vt, g_vt); SYMB(v, g_v);     SYMB(tmp, g_tmp); SYMB(uo, g_uo);
    SYMF(posf, g_posf); SYMF(posg, g_posg); SYMF(mpart, g_mpart);
    SYMB(cctx, g_cctx); SYMB(cctx2, g_cctx2);
    SYMF(cbF, g_cbF); SYMF(cbG, g_cbG);
    SYMF(Ach, g_Ach); SYMF(Bchf, g_Bchf); SYMF(Bchb, g_Bchb);
    SYMF(Sinf, g_Sinf); SYMF(Sinb, g_Sinb);
    SYMF(xgt, g_xgt); SYMB(xgs, g_xgs); SYMB(ug, g_ug);
    SYMF(a2, g_a2);   SYMB(sg2, g_sg2); SYMB(o2, g_o2);   SYMB(yg, g_yg);

    dim3 tb(32, 8);

    // ---- fine branch ----
    trans_cn_nc<<<dim3(128, 8, Bb), tb>>>(x, xs, Nn);
    pos_up_k<<<Nn, Cc>>>(pf, posf);
    gemm(xs, 0, 0, 0, 1, 12, Wt, bt, posf, 4095, 0, 0, 0, u, Bb * Nn, 0);

    mean_part8<<<dim3(32, Bb), 256>>>(u, mpart, Nn, 32);
    ln_ctx_k<<<Bb, Cc>>>(mpart, 256, 1.f / Nn, lng, lnb, cctx);
    ctx_proj_k<<<dim3(3, Bb), Cc>>>(cctx, Wf, Wwm, Wo, bfb, bw, bo, cbF);

    // single fused gate GEMM: a (f32), sg (bf16), o (bf16); K=256
    gemm_gates(u, Wf, Wwm, Wo, cbF, 12, a_, sg, o_, Bb * Nn);

    scan_p1_bi<<<dim3(NCH, Bb), Cc>>>(a_, sg, u, Ach, Bchf, Bchb);
    scan_p2_bi<<<Bb, Cc>>>(Ach, Bchf, Bchb, Sinf, Sinb);
    scan_p3<<<dim3(NCH, Bb), Cc>>>(a_, sg, o_, u, Sinf, yf, 1);
    scan_p3<<<dim3(NCH, Bb), Cc>>>(a_, sg, o_, u, Sinb, yb, -1);

    // rho GEMM + blend fused
    gemm(u, yf, yb, 0, 3, 12, Wr, br, 0, 0, yf, 0, yb, y, Bb * Nn, 2);

    // ---- global branch ----
    avgpool_k<<<dim3(Cc, Bb), 256>>>(x, xgt);
    trans_cn_nc<<<dim3(8, 8, Bb), tb>>>(xgt, xgs, NG);
    pos_down_k<<<NG, Cc>>>(pg, posg);
    gemm(xgs, 0, 0, 0, 1, 8, Wt, bt, posg, 255, 0, 0, 0, ug, Bb * NG, 0);

    mean_part8<<<dim3(8, Bb), 256>>>(ug, mpart, NG, 8);
    ln_ctx_k<<<Bb, Cc>>>(mpart, 64, 1.f / NG, lng, lnb, cctx2);
    ctx_proj_k<<<dim3(3, Bb), Cc>>>(cctx2, Wf, Wwm, Wo, bfb, bw, bo, cbG);

    gemm_gates(ug, Wf, Wwm, Wo, cbG, 8, a2, sg2, o2, Bb * NG);
    scan_fwd_simple<<<Bb, Cc>>>(a2, sg2, o2, ug, yg, NG);
    upsample_g<<<dim3(Nn, Bb), Cc>>>(yg, ygs);

    // lam GEMM + blend fused: z = y + sig(..)*ygs
    gemm(y, ygs, u, 0, 3, 12, Wgi, bgi, 0, 0, y, 0, ygs, z, Bb * Nn, 3);

    // ---- local depthwise branch ----
    dwconv_k<<<dim3(16, Cc, Bb), 256>>>(x, dww, dwb, vmap);
    trans_cn_nc_bf<<<dim3(128, 8, Bb), tb>>>(vmap, vt, Nn);
    gemm(vt, 0, 0, 0, 1, 12, Wl, bl, 0, 0, 0, 0, 0, v, Bb * Nn, 0);
    // eta GEMM + blend fused
    gemm(v, z, 0, 0, 2, 12, Wlf, blf, 0, 0, v, 0, z, uo, Bb * Nn, 2);

    // ---- output proj + residual ----
    gemm(uo, 0, 0, 0, 1, 12, Wout, bout, 0, 0, 0, 0, 0, tmp, Bb * Nn, 0);
    trans_add_k<<<dim3(128, 8, Bb), tb>>>(tmp, x, outp);
}